// round 3
// baseline (speedup 1.0000x reference)
#include <cuda_runtime.h>

typedef unsigned long long u64;

#define SEQ   20
#define FEAT  5
#define NU1   10
#define NU2   7
#define NU3   4
#define NOUT  4
#define NBATCH 262144
#define NTHREADS 128
#define EPB (NTHREADS * 2)          // elements per block (2 per thread)

// ---------------- packed f32x2 helpers ----------------
__device__ __forceinline__ u64 pack2(float lo, float hi) {
    u64 r; asm("mov.b64 %0, {%1, %2};" : "=l"(r) : "f"(lo), "f"(hi)); return r;
}
__device__ __forceinline__ u64 dup2(float s) {
    u64 r; asm("mov.b64 %0, {%1, %1};" : "=l"(r) : "f"(s)); return r;
}
__device__ __forceinline__ void unpack2(u64 v, float& lo, float& hi) {
    asm("mov.b64 {%0, %1}, %2;" : "=f"(lo), "=f"(hi) : "l"(v));
}
__device__ __forceinline__ u64 ffma2(u64 a, u64 b, u64 c) {
    u64 d; asm("fma.rn.f32x2 %0, %1, %2, %3;" : "=l"(d) : "l"(a), "l"(b), "l"(c)); return d;
}
__device__ __forceinline__ u64 fmul2(u64 a, u64 b) {
    u64 d; asm("mul.rn.f32x2 %0, %1, %2;" : "=l"(d) : "l"(a), "l"(b)); return d;
}

// ---------------- single-MUFU nonlinearities ----------------
__device__ __forceinline__ float tanh1(float x) {
    float y; asm("tanh.approx.f32 %0, %1;" : "=f"(y) : "f"(x)); return y;
}
__device__ __forceinline__ u64 tanh2(u64 v) {
    float a, b; unpack2(v, a, b);
    return pack2(tanh1(a), tanh1(b));
}
// sigmoid(x) = 0.5*tanh(x/2)+0.5 ; the /2 is pre-folded into i/f/o weights.
__device__ __forceinline__ u64 sigh2(u64 zhalf, u64 H2) {
    return ffma2(tanh2(zhalf), H2, H2);
}

// ---------------- shared-memory layout (float offsets into dynamic smem) ------
// Weight rows: D (Wk) then U (Wr); per row PH unit-pairs x 4 gates (pair = u64).
constexpr int OFF_W1 = 0;      // 15 * 5 * 4 * 2 = 600
constexpr int OFF_B1 = 600;    // 5*4*2 = 40
constexpr int OFF_W2 = 640;    // 17 * 4 * 4 * 2 = 544 (U2 padded 7->8)
constexpr int OFF_B2 = 1184;   // 32
constexpr int OFF_W3 = 1216;   // 11 * 2 * 4 * 2 = 176
constexpr int OFF_B3 = 1392;   // 16
constexpr int OFF_WD = 1408;   // 16
constexpr int OFF_BD = 1424;   // 4
constexpr int OFF_XS = 1428;   // x staging: EPB rows * 101 floats
constexpr int XSTRIDE = 101;   // odd stride -> conflict-free scalar LDS
constexpr int SMEM_FLOATS = OFF_XS + EPB * XSTRIDE;   // 1428 + 25856 = 27284
constexpr int SMEM_BYTES  = SMEM_FLOATS * 4;          // 109136 B

// gate scale: i,f,o get 0.5 (sigmoid-via-tanh), g gets 1.0
__device__ __forceinline__ float gate_scale(int g) { return (g == 2) ? 1.0f : 0.5f; }

__device__ __forceinline__ void load_wcomb(float* dst, const float* __restrict__ Wk,
                                           const float* __restrict__ Wr,
                                           int D, int U, int PH) {
    int total = (D + U) * PH * 4;
    for (int idx = threadIdx.x; idx < total; idx += blockDim.x) {
        int row = idx / (PH * 4);
        int rem = idx - row * (PH * 4);
        int p = rem >> 2, g = rem & 3;
        const float* src = (row < D) ? (Wk + row * 4 * U) : (Wr + (row - D) * 4 * U);
        float sc = gate_scale(g);
        int u0 = 2 * p, u1 = u0 + 1;
        dst[2 * idx]     = (u0 < U) ? sc * src[g * U + u0] : 0.0f;
        dst[2 * idx + 1] = (u1 < U) ? sc * src[g * U + u1] : 0.0f;
    }
}
__device__ __forceinline__ void load_bias(float* dst, const float* __restrict__ b,
                                          int U, int PH) {
    int total = PH * 4;
    for (int idx = threadIdx.x; idx < total; idx += blockDim.x) {
        int p = idx >> 2, g = idx & 3;
        float sc = gate_scale(g);
        int u0 = 2 * p, u1 = u0 + 1;
        dst[2 * idx]     = (u0 < U) ? sc * b[g * U + u0] : 0.0f;
        dst[2 * idx + 1] = (u1 < U) ? sc * b[g * U + u1] : 0.0f;
    }
}

// ---------------- LSTM layer step, 2 batch elements sharing weight loads ------
template<int NROWS, int PH>
__device__ __forceinline__ void layer_step2(const u64* __restrict__ ma,
                                            const u64* __restrict__ mb,
                                            u64* ha, u64* ca, u64* hb, u64* cb,
                                            const float* __restrict__ w,
                                            const float* __restrict__ bias, u64 H2) {
#pragma unroll
    for (int p = 0; p < PH; p++) {
        ulonglong2 bv0 = *(const ulonglong2*)(bias + p * 8);
        ulonglong2 bv1 = *(const ulonglong2*)(bias + p * 8 + 4);
        u64 zaa = bv0.x, zfa = bv0.y, zga = bv1.x, zoa = bv1.y;
        u64 zab = bv0.x, zfb = bv0.y, zgb = bv1.x, zob = bv1.y;
#pragma unroll
        for (int k = 0; k < NROWS; k++) {
            const float* row = w + (k * PH + p) * 8;
            ulonglong2 w0 = *(const ulonglong2*)(row);
            ulonglong2 w1 = *(const ulonglong2*)(row + 4);
            u64 va = ma[k], vb = mb[k];
            zaa = ffma2(va, w0.x, zaa); zfa = ffma2(va, w0.y, zfa);
            zga = ffma2(va, w1.x, zga); zoa = ffma2(va, w1.y, zoa);
            zab = ffma2(vb, w0.x, zab); zfb = ffma2(vb, w0.y, zfb);
            zgb = ffma2(vb, w1.x, zgb); zob = ffma2(vb, w1.y, zob);
        }
        {
            u64 iv = sigh2(zaa, H2), fv = sigh2(zfa, H2), gv = tanh2(zga), ov = sigh2(zoa, H2);
            u64 cn = ffma2(fv, ca[p], fmul2(iv, gv));
            ca[p] = cn;
            ha[p] = fmul2(ov, tanh2(cn));
        }
        {
            u64 iv = sigh2(zab, H2), fv = sigh2(zfb, H2), gv = tanh2(zgb), ov = sigh2(zob, H2);
            u64 cn = ffma2(fv, cb[p], fmul2(iv, gv));
            cb[p] = cn;
            hb[p] = fmul2(ov, tanh2(cn));
        }
    }
}

template<int NP>
__device__ __forceinline__ void dup_from_pairs(u64* dst, const u64* h) {
#pragma unroll
    for (int j = 0; j < NP; j++) {
        float a, b; unpack2(h[j], a, b);
        dst[2 * j]     = dup2(a);
        dst[2 * j + 1] = dup2(b);
    }
}

// ---------------- fused kernel ----------------
__global__ void __launch_bounds__(NTHREADS, 2)
lstm3_kernel(const float* __restrict__ x,
             const float* __restrict__ Wk1, const float* __restrict__ Wr1, const float* __restrict__ b1,
             const float* __restrict__ Wk2, const float* __restrict__ Wr2, const float* __restrict__ b2,
             const float* __restrict__ Wk3, const float* __restrict__ Wr3, const float* __restrict__ b3,
             const float* __restrict__ Wd,  const float* __restrict__ bd,
             float* __restrict__ out) {
    extern __shared__ float s[];

    // weights (pre-scaled for sigmoid-via-tanh)
    load_wcomb(s + OFF_W1, Wk1, Wr1, FEAT, NU1, 5);
    load_bias (s + OFF_B1, b1, NU1, 5);
    load_wcomb(s + OFF_W2, Wk2, Wr2, NU1, NU2, 4);
    load_bias (s + OFF_B2, b2, NU2, 4);
    load_wcomb(s + OFF_W3, Wk3, Wr3, NU2, NU3, 2);
    load_bias (s + OFF_B3, b3, NU3, 2);
    for (int idx = threadIdx.x; idx < 8; idx += blockDim.x) {
        int k = idx >> 1, p = idx & 1;
        s[OFF_WD + 2 * idx]     = 0.5f * Wd[k * 4 + 2 * p];
        s[OFF_WD + 2 * idx + 1] = 0.5f * Wd[k * 4 + 2 * p + 1];
    }
    for (int idx = threadIdx.x; idx < 4; idx += blockDim.x)
        s[OFF_BD + idx] = 0.5f * bd[idx];

    // stage this block's 256 x-rows coalesced into smem (row stride 101)
    {
        const float4* x4 = (const float4*)(x + (size_t)blockIdx.x * EPB * (SEQ * FEAT));
        float* xs = s + OFF_XS;
        for (int i = threadIdx.x; i < EPB * (SEQ * FEAT / 4); i += NTHREADS) {
            int row = i / 25, c4 = i - row * 25;
            float4 v = x4[row * 25 + c4];
            float* q = xs + row * XSTRIDE + c4 * 4;
            q[0] = v.x; q[1] = v.y; q[2] = v.z; q[3] = v.w;
        }
    }
    __syncthreads();

    const int tid = threadIdx.x;
    const u64 H2 = pack2(0.5f, 0.5f);
    const float* xsa = s + OFF_XS + tid * XSTRIDE;
    const float* xsb = xsa + NTHREADS * XSTRIDE;
    const int gid = blockIdx.x * EPB + tid;
    float* oa = out + (size_t)gid * (SEQ * NOUT);
    float* ob = oa + (size_t)NTHREADS * (SEQ * NOUT);

    u64 h1a[5], c1a[5], h2a[4], c2a[4], h3a[2], c3a[2];
    u64 h1b[5], c1b[5], h2b[4], c2b[4], h3b[2], c3b[2];
#pragma unroll
    for (int i = 0; i < 5; i++) { h1a[i]=c1a[i]=h1b[i]=c1b[i]=0ull; }
#pragma unroll
    for (int i = 0; i < 4; i++) { h2a[i]=c2a[i]=h2b[i]=c2b[i]=0ull; }
#pragma unroll
    for (int i = 0; i < 2; i++) { h3a[i]=c3a[i]=h3b[i]=c3b[i]=0ull; }

#pragma unroll 1
    for (int t = 0; t < SEQ; t++) {
        // ---- layer 1 : rows = 5 x + 10 h ----
        u64 m1a[15], m1b[15];
#pragma unroll
        for (int k = 0; k < FEAT; k++) {
            m1a[k] = dup2(xsa[t * FEAT + k]);
            m1b[k] = dup2(xsb[t * FEAT + k]);
        }
        dup_from_pairs<5>(m1a + 5, h1a);
        dup_from_pairs<5>(m1b + 5, h1b);
        layer_step2<15, 5>(m1a, m1b, h1a, c1a, h1b, c1b, s + OFF_W1, s + OFF_B1, H2);

        // ---- layer 2 : rows = 10 h1 + 7 h2 (units padded to 8) ----
        u64 m2a[17], m2b[17];
        dup_from_pairs<5>(m2a, h1a);
        dup_from_pairs<5>(m2b, h1b);
        dup_from_pairs<3>(m2a + 10, h2a);
        dup_from_pairs<3>(m2b + 10, h2b);
        { float u, v; unpack2(h2a[3], u, v); m2a[16] = dup2(u); (void)v; }
        { float u, v; unpack2(h2b[3], u, v); m2b[16] = dup2(u); (void)v; }
        layer_step2<17, 4>(m2a, m2b, h2a, c2a, h2b, c2b, s + OFF_W2, s + OFF_B2, H2);

        // ---- layer 3 : rows = 7 h2 + 4 h3 ----
        u64 m3a[11], m3b[11];
        dup_from_pairs<3>(m3a, h2a);
        dup_from_pairs<3>(m3b, h2b);
        { float u, v; unpack2(h2a[3], u, v); m3a[6] = dup2(u); (void)v; }
        { float u, v; unpack2(h2b[3], u, v); m3b[6] = dup2(u); (void)v; }
        dup_from_pairs<2>(m3a + 7, h3a);
        dup_from_pairs<2>(m3b + 7, h3b);
        layer_step2<11, 2>(m3a, m3b, h3a, c3a, h3b, c3b, s + OFF_W3, s + OFF_B3, H2);

        // ---- dense 4x4 + sigmoid (weights pre-halved) ----
        ulonglong2 bdv = *(const ulonglong2*)(s + OFF_BD);
#pragma unroll
        for (int e = 0; e < 2; e++) {
            const u64* h3 = e ? h3b : h3a;
            u64 z0 = bdv.x, z1 = bdv.y;
            float hs0, hs1, hs2, hs3;
            unpack2(h3[0], hs0, hs1);
            unpack2(h3[1], hs2, hs3);
            float hsv[4] = {hs0, hs1, hs2, hs3};
#pragma unroll
            for (int k = 0; k < 4; k++) {
                u64 m = dup2(hsv[k]);
                ulonglong2 w = *(const ulonglong2*)(s + OFF_WD + k * 4);
                z0 = ffma2(m, w.x, z0);
                z1 = ffma2(m, w.y, z1);
            }
            u64 r0 = sigh2(z0, H2), r1 = sigh2(z1, H2);
            float o0, o1, o2, o3;
            unpack2(r0, o0, o1);
            unpack2(r1, o2, o3);
            float* op = (e ? ob : oa) + t * NOUT;
            *(float4*)op = make_float4(o0, o1, o2, o3);
        }
    }
}

extern "C" void kernel_launch(void* const* d_in, const int* in_sizes, int n_in,
                              void* d_out, int out_size) {
    const float* x   = (const float*)d_in[0];
    const float* Wk1 = (const float*)d_in[1];
    const float* Wr1 = (const float*)d_in[2];
    const float* b1  = (const float*)d_in[3];
    const float* Wk2 = (const float*)d_in[4];
    const float* Wr2 = (const float*)d_in[5];
    const float* b2  = (const float*)d_in[6];
    const float* Wk3 = (const float*)d_in[7];
    const float* Wr3 = (const float*)d_in[8];
    const float* b3  = (const float*)d_in[9];
    const float* Wd  = (const float*)d_in[10];
    const float* bd  = (const float*)d_in[11];

    cudaFuncSetAttribute(lstm3_kernel, cudaFuncAttributeMaxDynamicSharedMemorySize, SMEM_BYTES);

    lstm3_kernel<<<NBATCH / EPB, NTHREADS, SMEM_BYTES>>>(
        x, Wk1, Wr1, b1, Wk2, Wr2, b2, Wk3, Wr3, b3, Wd, bd, (float*)d_out);
}

// round 4
// speedup vs baseline: 1.0188x; 1.0188x over previous
#include <cuda_runtime.h>

typedef unsigned long long u64;

#define SEQ   20
#define FEAT  5
#define NU1   10
#define NU2   7
#define NU3   4
#define NOUT  4
#define NBATCH 262144
#define NTHREADS 128

// ---------------- packed f32x2 helpers ----------------
__device__ __forceinline__ u64 pack2(float lo, float hi) {
    u64 r; asm("mov.b64 %0, {%1, %2};" : "=l"(r) : "f"(lo), "f"(hi)); return r;
}
__device__ __forceinline__ u64 dup2(float s) {
    u64 r; asm("mov.b64 %0, {%1, %1};" : "=l"(r) : "f"(s)); return r;
}
__device__ __forceinline__ void unpack2(u64 v, float& lo, float& hi) {
    asm("mov.b64 {%0, %1}, %2;" : "=f"(lo), "=f"(hi) : "l"(v));
}
__device__ __forceinline__ u64 ffma2(u64 a, u64 b, u64 c) {
    u64 d; asm("fma.rn.f32x2 %0, %1, %2, %3;" : "=l"(d) : "l"(a), "l"(b), "l"(c)); return d;
}
__device__ __forceinline__ u64 fmul2(u64 a, u64 b) {
    u64 d; asm("mul.rn.f32x2 %0, %1, %2;" : "=l"(d) : "l"(a), "l"(b)); return d;
}

// ---------------- single-MUFU nonlinearities ----------------
__device__ __forceinline__ float tanh1(float x) {
    float y; asm("tanh.approx.f32 %0, %1;" : "=f"(y) : "f"(x)); return y;
}
__device__ __forceinline__ u64 tanh2(u64 v) {
    float a, b; unpack2(v, a, b);
    return pack2(tanh1(a), tanh1(b));
}
// sigmoid(x) = 0.5*tanh(x/2) + 0.5 ; the /2 is pre-folded into i/f/o weights.
__device__ __forceinline__ u64 sigh2(u64 zhalf, u64 H2) {
    return ffma2(tanh2(zhalf), H2, H2);
}

// ---------------- shared-memory layout (float offsets, dynamic smem) ----------
constexpr int OFF_W1 = 0;      // 15 rows * 5 PH * 4 g * 2 = 600
constexpr int OFF_B1 = 600;    // 40
constexpr int OFF_W2 = 640;    // 17 * 4 * 4 * 2 = 544 (U2 padded 7->8)
constexpr int OFF_B2 = 1184;   // 32
constexpr int OFF_W3 = 1216;   // 11 * 2 * 4 * 2 = 176
constexpr int OFF_B3 = 1392;   // 16
constexpr int OFF_WD = 1408;   // 16
constexpr int OFF_BD = 1424;   // 4
constexpr int OFF_XS = 1428;   // x staged transposed: [100 cols][NTHREADS]
constexpr int SMEM_FLOATS = OFF_XS + SEQ * FEAT * NTHREADS;  // 1428 + 12800
constexpr int SMEM_BYTES  = SMEM_FLOATS * 4;                 // 56912 B

// gate scale: i,f,o get 0.5 (sigmoid-via-tanh), g(cell) gets 1.0
__device__ __forceinline__ float gate_scale(int g) { return (g == 2) ? 1.0f : 0.5f; }

__device__ __forceinline__ void load_wcomb(float* dst, const float* __restrict__ Wk,
                                           const float* __restrict__ Wr,
                                           int D, int U, int PH) {
    int total = (D + U) * PH * 4;
    for (int idx = threadIdx.x; idx < total; idx += blockDim.x) {
        int row = idx / (PH * 4);
        int rem = idx - row * (PH * 4);
        int p = rem >> 2, g = rem & 3;
        const float* src = (row < D) ? (Wk + row * 4 * U) : (Wr + (row - D) * 4 * U);
        float sc = gate_scale(g);
        int u0 = 2 * p, u1 = u0 + 1;
        dst[2 * idx]     = (u0 < U) ? sc * src[g * U + u0] : 0.0f;
        dst[2 * idx + 1] = (u1 < U) ? sc * src[g * U + u1] : 0.0f;
    }
}
__device__ __forceinline__ void load_bias(float* dst, const float* __restrict__ b,
                                          int U, int PH) {
    int total = PH * 4;
    for (int idx = threadIdx.x; idx < total; idx += blockDim.x) {
        int p = idx >> 2, g = idx & 3;
        float sc = gate_scale(g);
        int u0 = 2 * p, u1 = u0 + 1;
        dst[2 * idx]     = (u0 < U) ? sc * b[g * U + u0] : 0.0f;
        dst[2 * idx + 1] = (u1 < U) ? sc * b[g * U + u1] : 0.0f;
    }
}

// ---------------- one LSTM layer step (single element, pair-packed units) -----
template<int NROWS, int PH>
__device__ __forceinline__ void layer_step(const u64* __restrict__ mult, u64* h, u64* c,
                                           const float* __restrict__ w,
                                           const float* __restrict__ bias, u64 H2) {
#pragma unroll
    for (int p = 0; p < PH; p++) {
        ulonglong2 bv0 = *(const ulonglong2*)(bias + p * 8);
        ulonglong2 bv1 = *(const ulonglong2*)(bias + p * 8 + 4);
        u64 za = bv0.x, zf = bv0.y, zg = bv1.x, zo = bv1.y;
#pragma unroll
        for (int k = 0; k < NROWS; k++) {
            const float* row = w + (k * PH + p) * 8;
            ulonglong2 w0 = *(const ulonglong2*)(row);
            ulonglong2 w1 = *(const ulonglong2*)(row + 4);
            u64 m = mult[k];
            za = ffma2(m, w0.x, za);
            zf = ffma2(m, w0.y, zf);
            zg = ffma2(m, w1.x, zg);
            zo = ffma2(m, w1.y, zo);
        }
        u64 iv = sigh2(za, H2), fv = sigh2(zf, H2), gv = tanh2(zg), ov = sigh2(zo, H2);
        u64 cn = ffma2(fv, c[p], fmul2(iv, gv));
        c[p] = cn;
        h[p] = fmul2(ov, tanh2(cn));
    }
}

template<int NP>
__device__ __forceinline__ void dup_from_pairs(u64* dst, const u64* h) {
#pragma unroll
    for (int j = 0; j < NP; j++) {
        float a, b; unpack2(h[j], a, b);
        dst[2 * j]     = dup2(a);
        dst[2 * j + 1] = dup2(b);
    }
}

// ---------------- fused kernel ----------------
__global__ void __launch_bounds__(NTHREADS, 4)
lstm3_kernel(const float* __restrict__ x,
             const float* __restrict__ Wk1, const float* __restrict__ Wr1, const float* __restrict__ b1,
             const float* __restrict__ Wk2, const float* __restrict__ Wr2, const float* __restrict__ b2,
             const float* __restrict__ Wk3, const float* __restrict__ Wr3, const float* __restrict__ b3,
             const float* __restrict__ Wd,  const float* __restrict__ bd,
             float* __restrict__ out) {
    extern __shared__ float s[];

    load_wcomb(s + OFF_W1, Wk1, Wr1, FEAT, NU1, 5);
    load_bias (s + OFF_B1, b1, NU1, 5);
    load_wcomb(s + OFF_W2, Wk2, Wr2, NU1, NU2, 4);
    load_bias (s + OFF_B2, b2, NU2, 4);
    load_wcomb(s + OFF_W3, Wk3, Wr3, NU2, NU3, 2);
    load_bias (s + OFF_B3, b3, NU3, 2);
    for (int idx = threadIdx.x; idx < 8; idx += blockDim.x) {
        int k = idx >> 1, p = idx & 1;
        s[OFF_WD + 2 * idx]     = 0.5f * Wd[k * 4 + 2 * p];
        s[OFF_WD + 2 * idx + 1] = 0.5f * Wd[k * 4 + 2 * p + 1];
    }
    for (int idx = threadIdx.x; idx < 4; idx += blockDim.x)
        s[OFF_BD + idx] = 0.5f * bd[idx];

    // stage this block's 128 x-rows into smem, transposed [col][tid]:
    // reads are L1-local (each thread streams its own 400B row), writes conflict-free.
    {
        const int tid = threadIdx.x;
        const float4* xrow4 = (const float4*)(x + (size_t)(blockIdx.x * NTHREADS + tid) * (SEQ * FEAT));
        float* xs = s + OFF_XS;
#pragma unroll
        for (int c4 = 0; c4 < SEQ * FEAT / 4; c4++) {
            float4 v = xrow4[c4];
            xs[(c4 * 4 + 0) * NTHREADS + tid] = v.x;
            xs[(c4 * 4 + 1) * NTHREADS + tid] = v.y;
            xs[(c4 * 4 + 2) * NTHREADS + tid] = v.z;
            xs[(c4 * 4 + 3) * NTHREADS + tid] = v.w;
        }
    }
    __syncthreads();

    const int tid = threadIdx.x;
    const u64 H2 = pack2(0.5f, 0.5f);
    const float* xs = s + OFF_XS + tid;
    float* op = out + (size_t)(blockIdx.x * NTHREADS + tid) * (SEQ * NOUT);

    u64 h1[5], c1[5], h2[4], c2[4], h3[2], c3[2];
#pragma unroll
    for (int i = 0; i < 5; i++) { h1[i] = c1[i] = 0ull; }
#pragma unroll
    for (int i = 0; i < 4; i++) { h2[i] = c2[i] = 0ull; }
#pragma unroll
    for (int i = 0; i < 2; i++) { h3[i] = c3[i] = 0ull; }

#pragma unroll 1
    for (int t = 0; t < SEQ; t++) {
        // ---- layer 1 : rows = 5 x + 10 h ----
        u64 m1[15];
#pragma unroll
        for (int k = 0; k < FEAT; k++)
            m1[k] = dup2(xs[(t * FEAT + k) * NTHREADS]);
        dup_from_pairs<5>(m1 + 5, h1);
        layer_step<15, 5>(m1, h1, c1, s + OFF_W1, s + OFF_B1, H2);

        // ---- layer 2 : rows = 10 h1 + 7 h2 (units padded to 8) ----
        u64 m2[17];
        dup_from_pairs<5>(m2, h1);
        dup_from_pairs<3>(m2 + 10, h2);
        { float u, v; unpack2(h2[3], u, v); m2[16] = dup2(u); (void)v; }
        layer_step<17, 4>(m2, h2, c2, s + OFF_W2, s + OFF_B2, H2);

        // ---- layer 3 : rows = 7 h2 + 4 h3 ----
        u64 m3[11];
        dup_from_pairs<3>(m3, h2);
        { float u, v; unpack2(h2[3], u, v); m3[6] = dup2(u); (void)v; }
        dup_from_pairs<2>(m3 + 7, h3);
        layer_step<11, 2>(m3, h3, c3, s + OFF_W3, s + OFF_B3, H2);

        // ---- dense 4x4 + sigmoid (weights pre-halved) ----
        ulonglong2 bdv = *(const ulonglong2*)(s + OFF_BD);
        u64 z0 = bdv.x, z1 = bdv.y;
        float hs0, hs1, hs2, hs3;
        unpack2(h3[0], hs0, hs1);
        unpack2(h3[1], hs2, hs3);
        float hsv[4] = {hs0, hs1, hs2, hs3};
#pragma unroll
        for (int k = 0; k < 4; k++) {
            u64 m = dup2(hsv[k]);
            ulonglong2 w = *(const ulonglong2*)(s + OFF_WD + k * 4);
            z0 = ffma2(m, w.x, z0);
            z1 = ffma2(m, w.y, z1);
        }
        u64 r0 = sigh2(z0, H2), r1 = sigh2(z1, H2);
        float o0, o1, o2, o3;
        unpack2(r0, o0, o1);
        unpack2(r1, o2, o3);
        *(float4*)(op + t * NOUT) = make_float4(o0, o1, o2, o3);
    }
}

extern "C" void kernel_launch(void* const* d_in, const int* in_sizes, int n_in,
                              void* d_out, int out_size) {
    const float* x   = (const float*)d_in[0];
    const float* Wk1 = (const float*)d_in[1];
    const float* Wr1 = (const float*)d_in[2];
    const float* b1  = (const float*)d_in[3];
    const float* Wk2 = (const float*)d_in[4];
    const float* Wr2 = (const float*)d_in[5];
    const float* b2  = (const float*)d_in[6];
    const float* Wk3 = (const float*)d_in[7];
    const float* Wr3 = (const float*)d_in[8];
    const float* b3  = (const float*)d_in[9];
    const float* Wd  = (const float*)d_in[10];
    const float* bd  = (const float*)d_in[11];

    cudaFuncSetAttribute(lstm3_kernel, cudaFuncAttributeMaxDynamicSharedMemorySize, SMEM_BYTES);

    lstm3_kernel<<<NBATCH / NTHREADS, NTHREADS, SMEM_BYTES>>>(
        x, Wk1, Wr1, b1, Wk2, Wr2, b2, Wk3, Wr3, b3, Wd, bd, (float*)d_out);
}

// round 5
// speedup vs baseline: 1.0622x; 1.0426x over previous
#include <cuda_runtime.h>

typedef unsigned long long u64;

#define SEQ   20
#define FEAT  5
#define NU1   10
#define NU2   7
#define NU3   4
#define NOUT  4
#define NBATCH 262144
#define NTHREADS 128
#define EPB (NTHREADS * 2)      // 2 batch elements per thread
#define TCHUNK 5                // timesteps staged per smem chunk

// ---------------- packed f32x2 helpers ----------------
__device__ __forceinline__ u64 pack2(float lo, float hi) {
    u64 r; asm("mov.b64 %0, {%1, %2};" : "=l"(r) : "f"(lo), "f"(hi)); return r;
}
__device__ __forceinline__ u64 dup2(float s) {
    u64 r; asm("mov.b64 %0, {%1, %1};" : "=l"(r) : "f"(s)); return r;
}
__device__ __forceinline__ void unpack2(u64 v, float& lo, float& hi) {
    asm("mov.b64 {%0, %1}, %2;" : "=f"(lo), "=f"(hi) : "l"(v));
}
__device__ __forceinline__ u64 ffma2(u64 a, u64 b, u64 c) {
    u64 d; asm("fma.rn.f32x2 %0, %1, %2, %3;" : "=l"(d) : "l"(a), "l"(b), "l"(c)); return d;
}
__device__ __forceinline__ u64 fmul2(u64 a, u64 b) {
    u64 d; asm("mul.rn.f32x2 %0, %1, %2;" : "=l"(d) : "l"(a), "l"(b)); return d;
}

// ---------------- single-MUFU nonlinearities ----------------
__device__ __forceinline__ float tanh1(float x) {
    float y; asm("tanh.approx.f32 %0, %1;" : "=f"(y) : "f"(x)); return y;
}
__device__ __forceinline__ u64 tanh2(u64 v) {
    float a, b; unpack2(v, a, b);
    return pack2(tanh1(a), tanh1(b));
}
// sigmoid(x) = 0.5*tanh(x/2) + 0.5 ; the /2 pre-folded into i/f/o weights.
__device__ __forceinline__ u64 sigh2(u64 zhalf, u64 H2) {
    return ffma2(tanh2(zhalf), H2, H2);
}

// ---------------- shared-memory layout (float offsets, dynamic smem) ----------
constexpr int OFF_W1 = 0;      // 15 rows * 5 PH * 4 g * 2 = 600
constexpr int OFF_B1 = 600;    // 40
constexpr int OFF_W2 = 640;    // 17 * 4 * 4 * 2 = 544 (U2 cols padded 7->8)
constexpr int OFF_B2 = 1184;   // 32
constexpr int OFF_W3 = 1216;   // 11 * 2 * 4 * 2 = 176
constexpr int OFF_B3 = 1392;   // 16
constexpr int OFF_WD = 1408;   // 16
constexpr int OFF_BD = 1424;   // 4
constexpr int OFF_XS = 1428;   // x chunk: [EPB rows][TCHUNK*FEAT cols], stride 25
constexpr int XCOLS  = TCHUNK * FEAT;                       // 25
constexpr int SMEM_FLOATS = OFF_XS + EPB * XCOLS;           // 1428 + 6400
constexpr int SMEM_BYTES  = SMEM_FLOATS * 4;                // 31312 B

// gate scale: i,f,o get 0.5 (sigmoid-via-tanh), g(cell) gets 1.0
__device__ __forceinline__ float gate_scale(int g) { return (g == 2) ? 1.0f : 0.5f; }

__device__ __forceinline__ void load_wcomb(float* dst, const float* __restrict__ Wk,
                                           const float* __restrict__ Wr,
                                           int D, int U, int PH) {
    int total = (D + U) * PH * 4;
    for (int idx = threadIdx.x; idx < total; idx += blockDim.x) {
        int row = idx / (PH * 4);
        int rem = idx - row * (PH * 4);
        int p = rem >> 2, g = rem & 3;
        const float* src = (row < D) ? (Wk + row * 4 * U) : (Wr + (row - D) * 4 * U);
        float sc = gate_scale(g);
        int u0 = 2 * p, u1 = u0 + 1;
        dst[2 * idx]     = (u0 < U) ? sc * src[g * U + u0] : 0.0f;
        dst[2 * idx + 1] = (u1 < U) ? sc * src[g * U + u1] : 0.0f;
    }
}
__device__ __forceinline__ void load_bias(float* dst, const float* __restrict__ b,
                                          int U, int PH) {
    int total = PH * 4;
    for (int idx = threadIdx.x; idx < total; idx += blockDim.x) {
        int p = idx >> 2, g = idx & 3;
        float sc = gate_scale(g);
        int u0 = 2 * p, u1 = u0 + 1;
        dst[2 * idx]     = (u0 < U) ? sc * b[g * U + u0] : 0.0f;
        dst[2 * idx + 1] = (u1 < U) ? sc * b[g * U + u1] : 0.0f;
    }
}

// ---------------- LSTM layer step: 2 elements share every weight load --------
// dA/dB: previous-layer outputs (D scalars). hA/hB: this layer's h (scalars,
// size >= 2*PH, updated in place). cA/cB: pair-packed cell state (PH u64).
template<int D, int U, int PH>
__device__ __forceinline__ void layer_step2(const float* __restrict__ dA,
                                            const float* __restrict__ dB,
                                            float* __restrict__ hA, float* __restrict__ hB,
                                            u64* __restrict__ cA, u64* __restrict__ cB,
                                            const float* __restrict__ w,
                                            const float* __restrict__ bias, u64 H2) {
    float oldA[U], oldB[U];
#pragma unroll
    for (int i = 0; i < U; i++) { oldA[i] = hA[i]; oldB[i] = hB[i]; }

#pragma unroll
    for (int p = 0; p < PH; p++) {
        ulonglong2 bv0 = *(const ulonglong2*)(bias + p * 8);
        ulonglong2 bv1 = *(const ulonglong2*)(bias + p * 8 + 4);
        u64 zaA = bv0.x, zfA = bv0.y, zgA = bv1.x, zoA = bv1.y;
        u64 zaB = bv0.x, zfB = bv0.y, zgB = bv1.x, zoB = bv1.y;
#pragma unroll
        for (int k = 0; k < D + U; k++) {
            float sA = (k < D) ? dA[k] : oldA[k - D];
            float sB = (k < D) ? dB[k] : oldB[k - D];
            u64 mA = dup2(sA);
            u64 mB = dup2(sB);
            const float* row = w + (k * PH + p) * 8;
            ulonglong2 w0 = *(const ulonglong2*)(row);
            ulonglong2 w1 = *(const ulonglong2*)(row + 4);
            zaA = ffma2(mA, w0.x, zaA); zfA = ffma2(mA, w0.y, zfA);
            zgA = ffma2(mA, w1.x, zgA); zoA = ffma2(mA, w1.y, zoA);
            zaB = ffma2(mB, w0.x, zaB); zfB = ffma2(mB, w0.y, zfB);
            zgB = ffma2(mB, w1.x, zgB); zoB = ffma2(mB, w1.y, zoB);
        }
        {
            u64 iv = sigh2(zaA, H2), fv = sigh2(zfA, H2), gv = tanh2(zgA), ov = sigh2(zoA, H2);
            u64 cn = ffma2(fv, cA[p], fmul2(iv, gv));
            cA[p] = cn;
            u64 hn = fmul2(ov, tanh2(cn));
            unpack2(hn, hA[2 * p], hA[2 * p + 1]);
        }
        {
            u64 iv = sigh2(zaB, H2), fv = sigh2(zfB, H2), gv = tanh2(zgB), ov = sigh2(zoB, H2);
            u64 cn = ffma2(fv, cB[p], fmul2(iv, gv));
            cB[p] = cn;
            u64 hn = fmul2(ov, tanh2(cn));
            unpack2(hn, hB[2 * p], hB[2 * p + 1]);
        }
    }
}

// ---------------- fused kernel ----------------
__global__ void __launch_bounds__(NTHREADS, 3)
lstm3_kernel(const float* __restrict__ x,
             const float* __restrict__ Wk1, const float* __restrict__ Wr1, const float* __restrict__ b1,
             const float* __restrict__ Wk2, const float* __restrict__ Wr2, const float* __restrict__ b2,
             const float* __restrict__ Wk3, const float* __restrict__ Wr3, const float* __restrict__ b3,
             const float* __restrict__ Wd,  const float* __restrict__ bd,
             float* __restrict__ out) {
    extern __shared__ float s[];

    load_wcomb(s + OFF_W1, Wk1, Wr1, FEAT, NU1, 5);
    load_bias (s + OFF_B1, b1, NU1, 5);
    load_wcomb(s + OFF_W2, Wk2, Wr2, NU1, NU2, 4);
    load_bias (s + OFF_B2, b2, NU2, 4);
    load_wcomb(s + OFF_W3, Wk3, Wr3, NU2, NU3, 2);
    load_bias (s + OFF_B3, b3, NU3, 2);
    for (int idx = threadIdx.x; idx < 8; idx += blockDim.x) {
        int k = idx >> 1, p = idx & 1;
        s[OFF_WD + 2 * idx]     = 0.5f * Wd[k * 4 + 2 * p];
        s[OFF_WD + 2 * idx + 1] = 0.5f * Wd[k * 4 + 2 * p + 1];
    }
    for (int idx = threadIdx.x; idx < 4; idx += blockDim.x)
        s[OFF_BD + idx] = 0.5f * bd[idx];

    const int tid = threadIdx.x;
    const u64 H2 = pack2(0.5f, 0.5f);
    const float* gx = x + (size_t)blockIdx.x * EPB * (SEQ * FEAT);
    float* xs = s + OFF_XS;
    const int gidA = blockIdx.x * EPB + tid;
    float* oA = out + (size_t)gidA * (SEQ * NOUT);
    float* oB = oA + (size_t)NTHREADS * (SEQ * NOUT);

    // state: h as scalars, c as pair-packed u64
    float h1A[NU1], h1B[NU1], h2A[8], h2B[8], h3A[NU3], h3B[NU3];
    u64 c1A[5], c1B[5], c2A[4], c2B[4], c3A[2], c3B[2];
#pragma unroll
    for (int i = 0; i < NU1; i++) { h1A[i] = h1B[i] = 0.0f; }
#pragma unroll
    for (int i = 0; i < 8; i++)   { h2A[i] = h2B[i] = 0.0f; }
#pragma unroll
    for (int i = 0; i < NU3; i++) { h3A[i] = h3B[i] = 0.0f; }
#pragma unroll
    for (int i = 0; i < 5; i++) { c1A[i] = c1B[i] = 0ull; }
#pragma unroll
    for (int i = 0; i < 4; i++) { c2A[i] = c2B[i] = 0ull; }
#pragma unroll
    for (int i = 0; i < 2; i++) { c3A[i] = c3B[i] = 0ull; }

#pragma unroll 1
    for (int cc = 0; cc < SEQ / TCHUNK; cc++) {
        // stage TCHUNK timesteps of x for all EPB rows: xs[row][col], stride 25
        __syncthreads();
        for (int i = tid; i < EPB * XCOLS; i += NTHREADS) {
            int r = i / XCOLS, col = i - r * XCOLS;
            xs[i] = gx[r * (SEQ * FEAT) + cc * XCOLS + col];
        }
        __syncthreads();

#pragma unroll 1
        for (int ts = 0; ts < TCHUNK; ts++) {
            int t = cc * TCHUNK + ts;
            float xA[FEAT], xB[FEAT];
#pragma unroll
            for (int k = 0; k < FEAT; k++) {
                xA[k] = xs[tid * XCOLS + ts * FEAT + k];
                xB[k] = xs[(tid + NTHREADS) * XCOLS + ts * FEAT + k];
            }

            layer_step2<FEAT, NU1, 5>(xA,  xB,  h1A, h1B, c1A, c1B, s + OFF_W1, s + OFF_B1, H2);
            layer_step2<NU1,  NU2, 4>(h1A, h1B, h2A, h2B, c2A, c2B, s + OFF_W2, s + OFF_B2, H2);
            layer_step2<NU2,  NU3, 2>(h2A, h2B, h3A, h3B, c3A, c3B, s + OFF_W3, s + OFF_B3, H2);

            // dense 4x4 + sigmoid (weights pre-halved)
            ulonglong2 bdv = *(const ulonglong2*)(s + OFF_BD);
#pragma unroll
            for (int e = 0; e < 2; e++) {
                const float* h3 = e ? h3B : h3A;
                u64 z0 = bdv.x, z1 = bdv.y;
#pragma unroll
                for (int k = 0; k < NU3; k++) {
                    u64 m = dup2(h3[k]);
                    ulonglong2 w = *(const ulonglong2*)(s + OFF_WD + k * 4);
                    z0 = ffma2(m, w.x, z0);
                    z1 = ffma2(m, w.y, z1);
                }
                u64 r0 = sigh2(z0, H2), r1 = sigh2(z1, H2);
                float o0, o1, o2, o3;
                unpack2(r0, o0, o1);
                unpack2(r1, o2, o3);
                float* op = (e ? oB : oA) + t * NOUT;
                *(float4*)op = make_float4(o0, o1, o2, o3);
            }
        }
    }
}

extern "C" void kernel_launch(void* const* d_in, const int* in_sizes, int n_in,
                              void* d_out, int out_size) {
    const float* x   = (const float*)d_in[0];
    const float* Wk1 = (const float*)d_in[1];
    const float* Wr1 = (const float*)d_in[2];
    const float* b1  = (const float*)d_in[3];
    const float* Wk2 = (const float*)d_in[4];
    const float* Wr2 = (const float*)d_in[5];
    const float* b2  = (const float*)d_in[6];
    const float* Wk3 = (const float*)d_in[7];
    const float* Wr3 = (const float*)d_in[8];
    const float* b3  = (const float*)d_in[9];
    const float* Wd  = (const float*)d_in[10];
    const float* bd  = (const float*)d_in[11];

    cudaFuncSetAttribute(lstm3_kernel, cudaFuncAttributeMaxDynamicSharedMemorySize, SMEM_BYTES);

    lstm3_kernel<<<NBATCH / EPB, NTHREADS, SMEM_BYTES>>>(
        x, Wk1, Wr1, b1, Wk2, Wr2, b2, Wk3, Wr3, b3, Wd, bd, (float*)d_out);
}

// round 6
// speedup vs baseline: 10.7295x; 10.1017x over previous
#include <cuda_runtime.h>

typedef unsigned long long u64;

#define SEQ   20
#define FEAT  5
#define NU1   10
#define NU2   7
#define NU3   4
#define NOUT  4
#define NBATCH 262144
#define NTHREADS 128
#define EPB (NTHREADS * 2)      // 2 batch elements per thread
#define TCHUNK 5                // timesteps staged per smem chunk

// ---------------- packed f32x2 helpers ----------------
__device__ __forceinline__ u64 pack2(float lo, float hi) {
    u64 r; asm("mov.b64 %0, {%1, %2};" : "=l"(r) : "f"(lo), "f"(hi)); return r;
}
__device__ __forceinline__ u64 dup2(float s) {
    u64 r; asm("mov.b64 %0, {%1, %1};" : "=l"(r) : "f"(s)); return r;
}
__device__ __forceinline__ void unpack2(u64 v, float& lo, float& hi) {
    asm("mov.b64 {%0, %1}, %2;" : "=f"(lo), "=f"(hi) : "l"(v));
}
__device__ __forceinline__ u64 ffma2(u64 a, u64 b, u64 c) {
    u64 d; asm("fma.rn.f32x2 %0, %1, %2, %3;" : "=l"(d) : "l"(a), "l"(b), "l"(c)); return d;
}
__device__ __forceinline__ u64 fmul2(u64 a, u64 b) {
    u64 d; asm("mul.rn.f32x2 %0, %1, %2;" : "=l"(d) : "l"(a), "l"(b)); return d;
}

// ---------------- single-MUFU nonlinearities ----------------
__device__ __forceinline__ float tanh1(float x) {
    float y; asm("tanh.approx.f32 %0, %1;" : "=f"(y) : "f"(x)); return y;
}
__device__ __forceinline__ u64 tanh2(u64 v) {
    float a, b; unpack2(v, a, b);
    return pack2(tanh1(a), tanh1(b));
}
// sigmoid(x) = 0.5*tanh(x/2) + 0.5 ; the /2 pre-folded into i/f/o weights.
__device__ __forceinline__ u64 sigh2(u64 zhalf, u64 H2) {
    return ffma2(tanh2(zhalf), H2, H2);
}

// ---------------- shared-memory layout (float offsets, dynamic smem) ----------
constexpr int OFF_W1 = 0;      // 15 rows * 5 PH * 4 g * 2 = 600
constexpr int OFF_B1 = 600;    // 40
constexpr int OFF_W2 = 640;    // 17 * 4 * 4 * 2 = 544 (U2 cols padded 7->8)
constexpr int OFF_B2 = 1184;   // 32
constexpr int OFF_W3 = 1216;   // 11 * 2 * 4 * 2 = 176
constexpr int OFF_B3 = 1392;   // 16
constexpr int OFF_WD = 1408;   // 16
constexpr int OFF_BD = 1424;   // 4
constexpr int OFF_XS = 1428;   // x chunk: [EPB rows][TCHUNK*FEAT cols], stride 25
constexpr int XCOLS  = TCHUNK * FEAT;                       // 25
constexpr int SMEM_FLOATS = OFF_XS + EPB * XCOLS;           // 1428 + 6400
constexpr int SMEM_BYTES  = SMEM_FLOATS * 4;                // 31312 B

// gate scale: i,f,o get 0.5 (sigmoid-via-tanh), g(cell) gets 1.0
__device__ __forceinline__ float gate_scale(int g) { return (g == 2) ? 1.0f : 0.5f; }

__device__ __forceinline__ void load_wcomb(float* dst, const float* __restrict__ Wk,
                                           const float* __restrict__ Wr,
                                           int D, int U, int PH) {
    int total = (D + U) * PH * 4;
    for (int idx = threadIdx.x; idx < total; idx += blockDim.x) {
        int row = idx / (PH * 4);
        int rem = idx - row * (PH * 4);
        int p = rem >> 2, g = rem & 3;
        const float* src = (row < D) ? (Wk + row * 4 * U) : (Wr + (row - D) * 4 * U);
        float sc = gate_scale(g);
        int u0 = 2 * p, u1 = u0 + 1;
        dst[2 * idx]     = (u0 < U) ? sc * src[g * U + u0] : 0.0f;
        dst[2 * idx + 1] = (u1 < U) ? sc * src[g * U + u1] : 0.0f;
    }
}
__device__ __forceinline__ void load_bias(float* dst, const float* __restrict__ b,
                                          int U, int PH) {
    int total = PH * 4;
    for (int idx = threadIdx.x; idx < total; idx += blockDim.x) {
        int p = idx >> 2, g = idx & 3;
        float sc = gate_scale(g);
        int u0 = 2 * p, u1 = u0 + 1;
        dst[2 * idx]     = (u0 < U) ? sc * b[g * U + u0] : 0.0f;
        dst[2 * idx + 1] = (u1 < U) ? sc * b[g * U + u1] : 0.0f;
    }
}

// ---------------- LSTM layer step: 2 elements share every weight load --------
// p-loop deliberately NOT unrolled: only one unit-pair's 8 accumulators live at
// a time, containing register pressure; the k-loop stays unrolled for ILP.
template<int D, int U, int PH>
__device__ __forceinline__ void layer_step2(const float* __restrict__ dA,
                                            const float* __restrict__ dB,
                                            float* __restrict__ hA, float* __restrict__ hB,
                                            u64* __restrict__ cA, u64* __restrict__ cB,
                                            const float* __restrict__ w,
                                            const float* __restrict__ bias, u64 H2) {
    float oldA[U], oldB[U];
#pragma unroll
    for (int i = 0; i < U; i++) { oldA[i] = hA[i]; oldB[i] = hB[i]; }

#pragma unroll 1
    for (int p = 0; p < PH; p++) {
        ulonglong2 bv0 = *(const ulonglong2*)(bias + p * 8);
        ulonglong2 bv1 = *(const ulonglong2*)(bias + p * 8 + 4);
        u64 zaA = bv0.x, zfA = bv0.y, zgA = bv1.x, zoA = bv1.y;
        u64 zaB = bv0.x, zfB = bv0.y, zgB = bv1.x, zoB = bv1.y;
        const float* wp = w + p * 8;
#pragma unroll
        for (int k = 0; k < D + U; k++) {
            float sA = (k < D) ? dA[k] : oldA[k - D];
            float sB = (k < D) ? dB[k] : oldB[k - D];
            u64 mA = dup2(sA);
            u64 mB = dup2(sB);
            const float* row = wp + k * PH * 8;
            ulonglong2 w0 = *(const ulonglong2*)(row);
            ulonglong2 w1 = *(const ulonglong2*)(row + 4);
            zaA = ffma2(mA, w0.x, zaA); zfA = ffma2(mA, w0.y, zfA);
            zgA = ffma2(mA, w1.x, zgA); zoA = ffma2(mA, w1.y, zoA);
            zaB = ffma2(mB, w0.x, zaB); zfB = ffma2(mB, w0.y, zfB);
            zgB = ffma2(mB, w1.x, zgB); zoB = ffma2(mB, w1.y, zoB);
        }
        {
            u64 iv = sigh2(zaA, H2), fv = sigh2(zfA, H2), gv = tanh2(zgA), ov = sigh2(zoA, H2);
            u64 cn = ffma2(fv, cA[p], fmul2(iv, gv));
            cA[p] = cn;
            u64 hn = fmul2(ov, tanh2(cn));
            unpack2(hn, hA[2 * p], hA[2 * p + 1]);
        }
        {
            u64 iv = sigh2(zaB, H2), fv = sigh2(zfB, H2), gv = tanh2(zgB), ov = sigh2(zoB, H2);
            u64 cn = ffma2(fv, cB[p], fmul2(iv, gv));
            cB[p] = cn;
            u64 hn = fmul2(ov, tanh2(cn));
            unpack2(hn, hB[2 * p], hB[2 * p + 1]);
        }
    }
}

// ---------------- fused kernel ----------------
__global__ void __launch_bounds__(NTHREADS, 2)
lstm3_kernel(const float* __restrict__ x,
             const float* __restrict__ Wk1, const float* __restrict__ Wr1, const float* __restrict__ b1,
             const float* __restrict__ Wk2, const float* __restrict__ Wr2, const float* __restrict__ b2,
             const float* __restrict__ Wk3, const float* __restrict__ Wr3, const float* __restrict__ b3,
             const float* __restrict__ Wd,  const float* __restrict__ bd,
             float* __restrict__ out) {
    extern __shared__ float s[];

    load_wcomb(s + OFF_W1, Wk1, Wr1, FEAT, NU1, 5);
    load_bias (s + OFF_B1, b1, NU1, 5);
    load_wcomb(s + OFF_W2, Wk2, Wr2, NU1, NU2, 4);
    load_bias (s + OFF_B2, b2, NU2, 4);
    load_wcomb(s + OFF_W3, Wk3, Wr3, NU2, NU3, 2);
    load_bias (s + OFF_B3, b3, NU3, 2);
    for (int idx = threadIdx.x; idx < 8; idx += blockDim.x) {
        int k = idx >> 1, p = idx & 1;
        s[OFF_WD + 2 * idx]     = 0.5f * Wd[k * 4 + 2 * p];
        s[OFF_WD + 2 * idx + 1] = 0.5f * Wd[k * 4 + 2 * p + 1];
    }
    for (int idx = threadIdx.x; idx < 4; idx += blockDim.x)
        s[OFF_BD + idx] = 0.5f * bd[idx];

    const int tid = threadIdx.x;
    const u64 H2 = pack2(0.5f, 0.5f);
    const float* gx = x + (size_t)blockIdx.x * EPB * (SEQ * FEAT);
    float* xs = s + OFF_XS;
    const int gidA = blockIdx.x * EPB + tid;
    float* oA = out + (size_t)gidA * (SEQ * NOUT);
    float* oB = oA + (size_t)NTHREADS * (SEQ * NOUT);

    // state: h as scalars, c as pair-packed u64
    float h1A[NU1], h1B[NU1], h2A[8], h2B[8], h3A[NU3], h3B[NU3];
    u64 c1A[5], c1B[5], c2A[4], c2B[4], c3A[2], c3B[2];
#pragma unroll
    for (int i = 0; i < NU1; i++) { h1A[i] = h1B[i] = 0.0f; }
#pragma unroll
    for (int i = 0; i < 8; i++)   { h2A[i] = h2B[i] = 0.0f; }
#pragma unroll
    for (int i = 0; i < NU3; i++) { h3A[i] = h3B[i] = 0.0f; }
#pragma unroll
    for (int i = 0; i < 5; i++) { c1A[i] = c1B[i] = 0ull; }
#pragma unroll
    for (int i = 0; i < 4; i++) { c2A[i] = c2B[i] = 0ull; }
#pragma unroll
    for (int i = 0; i < 2; i++) { c3A[i] = c3B[i] = 0ull; }

#pragma unroll 1
    for (int cc = 0; cc < SEQ / TCHUNK; cc++) {
        // stage TCHUNK timesteps of x for all EPB rows: xs[row][col], stride 25
        __syncthreads();
        for (int i = tid; i < EPB * XCOLS; i += NTHREADS) {
            int r = i / XCOLS, col = i - r * XCOLS;
            xs[i] = gx[r * (SEQ * FEAT) + cc * XCOLS + col];
        }
        __syncthreads();

#pragma unroll 1
        for (int ts = 0; ts < TCHUNK; ts++) {
            int t = cc * TCHUNK + ts;
            float xA[FEAT], xB[FEAT];
#pragma unroll
            for (int k = 0; k < FEAT; k++) {
                xA[k] = xs[tid * XCOLS + ts * FEAT + k];
                xB[k] = xs[(tid + NTHREADS) * XCOLS + ts * FEAT + k];
            }

            layer_step2<FEAT, NU1, 5>(xA,  xB,  h1A, h1B, c1A, c1B, s + OFF_W1, s + OFF_B1, H2);
            layer_step2<NU1,  NU2, 4>(h1A, h1B, h2A, h2B, c2A, c2B, s + OFF_W2, s + OFF_B2, H2);
            layer_step2<NU2,  NU3, 2>(h2A, h2B, h3A, h3B, c3A, c3B, s + OFF_W3, s + OFF_B3, H2);

            // dense 4x4 + sigmoid (weights pre-halved)
            ulonglong2 bdv = *(const ulonglong2*)(s + OFF_BD);
#pragma unroll
            for (int e = 0; e < 2; e++) {
                const float* h3 = e ? h3B : h3A;
                u64 z0 = bdv.x, z1 = bdv.y;
#pragma unroll
                for (int k = 0; k < NU3; k++) {
                    u64 m = dup2(h3[k]);
                    ulonglong2 w = *(const ulonglong2*)(s + OFF_WD + k * 4);
                    z0 = ffma2(m, w.x, z0);
                    z1 = ffma2(m, w.y, z1);
                }
                u64 r0 = sigh2(z0, H2), r1 = sigh2(z1, H2);
                float o0, o1, o2, o3;
                unpack2(r0, o0, o1);
                unpack2(r1, o2, o3);
                float* op = (e ? oB : oA) + t * NOUT;
                *(float4*)op = make_float4(o0, o1, o2, o3);
            }
        }
    }
}

extern "C" void kernel_launch(void* const* d_in, const int* in_sizes, int n_in,
                              void* d_out, int out_size) {
    const float* x   = (const float*)d_in[0];
    const float* Wk1 = (const float*)d_in[1];
    const float* Wr1 = (const float*)d_in[2];
    const float* b1  = (const float*)d_in[3];
    const float* Wk2 = (const float*)d_in[4];
    const float* Wr2 = (const float*)d_in[5];
    const float* b2  = (const float*)d_in[6];
    const float* Wk3 = (const float*)d_in[7];
    const float* Wr3 = (const float*)d_in[8];
    const float* b3  = (const float*)d_in[9];
    const float* Wd  = (const float*)d_in[10];
    const float* bd  = (const float*)d_in[11];

    cudaFuncSetAttribute(lstm3_kernel, cudaFuncAttributeMaxDynamicSharedMemorySize, SMEM_BYTES);

    lstm3_kernel<<<NBATCH / EPB, NTHREADS, SMEM_BYTES>>>(
        x, Wk1, Wr1, b1, Wk2, Wr2, b2, Wk3, Wr3, b3, Wd, bd, (float*)d_out);
}

// round 7
// speedup vs baseline: 12.3265x; 1.1488x over previous
#include <cuda_runtime.h>

typedef unsigned long long u64;

#define SEQ   20
#define FEAT  5
#define NU1   10
#define NU2   7
#define NU3   4
#define NOUT  4
#define NBATCH 262144
#define NTHREADS 128
#define EPB (NTHREADS * 2)      // 2 batch elements per thread
#define TCHUNK 5                // timesteps staged per smem chunk

// ---------------- packed f32x2 helpers ----------------
__device__ __forceinline__ u64 pack2(float lo, float hi) {
    u64 r; asm("mov.b64 %0, {%1, %2};" : "=l"(r) : "f"(lo), "f"(hi)); return r;
}
__device__ __forceinline__ u64 dup2(float s) {
    u64 r; asm("mov.b64 %0, {%1, %1};" : "=l"(r) : "f"(s)); return r;
}
__device__ __forceinline__ void unpack2(u64 v, float& lo, float& hi) {
    asm("mov.b64 {%0, %1}, %2;" : "=f"(lo), "=f"(hi) : "l"(v));
}
__device__ __forceinline__ u64 ffma2(u64 a, u64 b, u64 c) {
    u64 d; asm("fma.rn.f32x2 %0, %1, %2, %3;" : "=l"(d) : "l"(a), "l"(b), "l"(c)); return d;
}
__device__ __forceinline__ u64 fmul2(u64 a, u64 b) {
    u64 d; asm("mul.rn.f32x2 %0, %1, %2;" : "=l"(d) : "l"(a), "l"(b)); return d;
}

// ---------------- single-MUFU nonlinearities ----------------
__device__ __forceinline__ float tanh1(float x) {
    float y; asm("tanh.approx.f32 %0, %1;" : "=f"(y) : "f"(x)); return y;
}
__device__ __forceinline__ u64 tanh2(u64 v) {
    float a, b; unpack2(v, a, b);
    return pack2(tanh1(a), tanh1(b));
}
// sigmoid(x) = 0.5*tanh(x/2) + 0.5 ; the /2 pre-folded into i/f/o weights.
__device__ __forceinline__ u64 sigh2(u64 zhalf, u64 H2) {
    return ffma2(tanh2(zhalf), H2, H2);
}

// ---------------- shared-memory layout (float offsets, dynamic smem) ----------
constexpr int OFF_W1 = 0;      // 15 rows * 5 PH * 4 g * 2 = 600
constexpr int OFF_B1 = 600;    // 40
constexpr int OFF_W2 = 640;    // 17 * 4 * 4 * 2 = 544 (U2 cols padded 7->8)
constexpr int OFF_B2 = 1184;   // 32
constexpr int OFF_W3 = 1216;   // 11 * 2 * 4 * 2 = 176
constexpr int OFF_B3 = 1392;   // 16
constexpr int OFF_WD = 1408;   // 16
constexpr int OFF_BD = 1424;   // 4
constexpr int OFF_XS = 1428;   // x chunk: [EPB rows][TCHUNK*FEAT cols], stride 25
constexpr int XCOLS  = TCHUNK * FEAT;                       // 25
constexpr int SMEM_FLOATS = OFF_XS + EPB * XCOLS;           // 1428 + 6400
constexpr int SMEM_BYTES  = SMEM_FLOATS * 4;                // 31312 B

// gate scale: i,f,o get 0.5 (sigmoid-via-tanh), g(cell) gets 1.0
__device__ __forceinline__ float gate_scale(int g) { return (g == 2) ? 1.0f : 0.5f; }

__device__ __forceinline__ void load_wcomb(float* dst, const float* __restrict__ Wk,
                                           const float* __restrict__ Wr,
                                           int D, int U, int PH) {
    int total = (D + U) * PH * 4;
    for (int idx = threadIdx.x; idx < total; idx += blockDim.x) {
        int row = idx / (PH * 4);
        int rem = idx - row * (PH * 4);
        int p = rem >> 2, g = rem & 3;
        const float* src = (row < D) ? (Wk + row * 4 * U) : (Wr + (row - D) * 4 * U);
        float sc = gate_scale(g);
        int u0 = 2 * p, u1 = u0 + 1;
        dst[2 * idx]     = (u0 < U) ? sc * src[g * U + u0] : 0.0f;
        dst[2 * idx + 1] = (u1 < U) ? sc * src[g * U + u1] : 0.0f;
    }
}
__device__ __forceinline__ void load_bias(float* dst, const float* __restrict__ b,
                                          int U, int PH) {
    int total = PH * 4;
    for (int idx = threadIdx.x; idx < total; idx += blockDim.x) {
        int p = idx >> 2, g = idx & 3;
        float sc = gate_scale(g);
        int u0 = 2 * p, u1 = u0 + 1;
        dst[2 * idx]     = (u0 < U) ? sc * b[g * U + u0] : 0.0f;
        dst[2 * idx + 1] = (u1 < U) ? sc * b[g * U + u1] : 0.0f;
    }
}

// ---------------- LSTM layer step: 2 elements share every weight load --------
// p-loop deliberately NOT unrolled (contains register pressure); k-loop fully
// unrolled for ILP. dA/dB may point to smem (layer 1: x) or to register arrays
// (layers 2/3: previous h) — compile-time-constant indexing keeps the latter
// in registers.
template<int D, int U, int PH>
__device__ __forceinline__ void layer_step2(const float* __restrict__ dA,
                                            const float* __restrict__ dB,
                                            float* __restrict__ hA, float* __restrict__ hB,
                                            u64* __restrict__ cA, u64* __restrict__ cB,
                                            const float* __restrict__ w,
                                            const float* __restrict__ bias, u64 H2) {
    float oldA[U], oldB[U];
#pragma unroll
    for (int i = 0; i < U; i++) { oldA[i] = hA[i]; oldB[i] = hB[i]; }

#pragma unroll 1
    for (int p = 0; p < PH; p++) {
        ulonglong2 bv0 = *(const ulonglong2*)(bias + p * 8);
        ulonglong2 bv1 = *(const ulonglong2*)(bias + p * 8 + 4);
        u64 zaA = bv0.x, zfA = bv0.y, zgA = bv1.x, zoA = bv1.y;
        u64 zaB = bv0.x, zfB = bv0.y, zgB = bv1.x, zoB = bv1.y;
        const float* wp = w + p * 8;
#pragma unroll
        for (int k = 0; k < D + U; k++) {
            float sA = (k < D) ? dA[k] : oldA[k - D];
            float sB = (k < D) ? dB[k] : oldB[k - D];
            u64 mA = dup2(sA);
            u64 mB = dup2(sB);
            const float* row = wp + k * PH * 8;
            ulonglong2 w0 = *(const ulonglong2*)(row);
            ulonglong2 w1 = *(const ulonglong2*)(row + 4);
            zaA = ffma2(mA, w0.x, zaA); zfA = ffma2(mA, w0.y, zfA);
            zgA = ffma2(mA, w1.x, zgA); zoA = ffma2(mA, w1.y, zoA);
            zaB = ffma2(mB, w0.x, zaB); zfB = ffma2(mB, w0.y, zfB);
            zgB = ffma2(mB, w1.x, zgB); zoB = ffma2(mB, w1.y, zoB);
        }
        {
            u64 iv = sigh2(zaA, H2), fv = sigh2(zfA, H2), gv = tanh2(zgA), ov = sigh2(zoA, H2);
            u64 cn = ffma2(fv, cA[p], fmul2(iv, gv));
            cA[p] = cn;
            u64 hn = fmul2(ov, tanh2(cn));
            unpack2(hn, hA[2 * p], hA[2 * p + 1]);
        }
        {
            u64 iv = sigh2(zaB, H2), fv = sigh2(zfB, H2), gv = tanh2(zgB), ov = sigh2(zoB, H2);
            u64 cn = ffma2(fv, cB[p], fmul2(iv, gv));
            cB[p] = cn;
            u64 hn = fmul2(ov, tanh2(cn));
            unpack2(hn, hB[2 * p], hB[2 * p + 1]);
        }
    }
}

// ---------------- fused kernel ----------------
__global__ void __launch_bounds__(NTHREADS, 3)
lstm3_kernel(const float* __restrict__ x,
             const float* __restrict__ Wk1, const float* __restrict__ Wr1, const float* __restrict__ b1,
             const float* __restrict__ Wk2, const float* __restrict__ Wr2, const float* __restrict__ b2,
             const float* __restrict__ Wk3, const float* __restrict__ Wr3, const float* __restrict__ b3,
             const float* __restrict__ Wd,  const float* __restrict__ bd,
             float* __restrict__ out) {
    extern __shared__ float s[];

    load_wcomb(s + OFF_W1, Wk1, Wr1, FEAT, NU1, 5);
    load_bias (s + OFF_B1, b1, NU1, 5);
    load_wcomb(s + OFF_W2, Wk2, Wr2, NU1, NU2, 4);
    load_bias (s + OFF_B2, b2, NU2, 4);
    load_wcomb(s + OFF_W3, Wk3, Wr3, NU2, NU3, 2);
    load_bias (s + OFF_B3, b3, NU3, 2);
    for (int idx = threadIdx.x; idx < 8; idx += blockDim.x) {
        int k = idx >> 1, p = idx & 1;
        s[OFF_WD + 2 * idx]     = 0.5f * Wd[k * 4 + 2 * p];
        s[OFF_WD + 2 * idx + 1] = 0.5f * Wd[k * 4 + 2 * p + 1];
    }
    for (int idx = threadIdx.x; idx < 4; idx += blockDim.x)
        s[OFF_BD + idx] = 0.5f * bd[idx];

    const int tid = threadIdx.x;
    const u64 H2 = pack2(0.5f, 0.5f);
    const float* gx = x + (size_t)blockIdx.x * EPB * (SEQ * FEAT);
    float* xs = s + OFF_XS;
    const int gidA = blockIdx.x * EPB + tid;
    float* oA = out + (size_t)gidA * (SEQ * NOUT);
    float* oB = oA + (size_t)NTHREADS * (SEQ * NOUT);

    // state: h as scalars, c as pair-packed u64
    float h1A[NU1], h1B[NU1], h2A[8], h2B[8], h3A[NU3], h3B[NU3];
    u64 c1A[5], c1B[5], c2A[4], c2B[4], c3A[2], c3B[2];
#pragma unroll
    for (int i = 0; i < NU1; i++) { h1A[i] = h1B[i] = 0.0f; }
#pragma unroll
    for (int i = 0; i < 8; i++)   { h2A[i] = h2B[i] = 0.0f; }
#pragma unroll
    for (int i = 0; i < NU3; i++) { h3A[i] = h3B[i] = 0.0f; }
#pragma unroll
    for (int i = 0; i < 5; i++) { c1A[i] = c1B[i] = 0ull; }
#pragma unroll
    for (int i = 0; i < 4; i++) { c2A[i] = c2B[i] = 0ull; }
#pragma unroll
    for (int i = 0; i < 2; i++) { c3A[i] = c3B[i] = 0ull; }

#pragma unroll 1
    for (int cc = 0; cc < SEQ / TCHUNK; cc++) {
        // stage TCHUNK timesteps of x for all EPB rows: xs[row][col], stride 25
        __syncthreads();
        for (int i = tid; i < EPB * XCOLS; i += NTHREADS) {
            int r = i / XCOLS, col = i - r * XCOLS;
            xs[i] = gx[r * (SEQ * FEAT) + cc * XCOLS + col];
        }
        __syncthreads();

#pragma unroll 1
        for (int ts = 0; ts < TCHUNK; ts++) {
            int t = cc * TCHUNK + ts;
            // layer-1 x inputs read directly from smem inside the k-loop
            // (stride 25 floats across tid -> conflict-free); saves 10 regs.
            const float* xA = xs + tid * XCOLS + ts * FEAT;
            const float* xB = xA + NTHREADS * XCOLS;

            layer_step2<FEAT, NU1, 5>(xA,  xB,  h1A, h1B, c1A, c1B, s + OFF_W1, s + OFF_B1, H2);
            layer_step2<NU1,  NU2, 4>(h1A, h1B, h2A, h2B, c2A, c2B, s + OFF_W2, s + OFF_B2, H2);
            layer_step2<NU2,  NU3, 2>(h2A, h2B, h3A, h3B, c3A, c3B, s + OFF_W3, s + OFF_B3, H2);

            // dense 4x4 + sigmoid (weights pre-halved)
            ulonglong2 bdv = *(const ulonglong2*)(s + OFF_BD);
#pragma unroll
            for (int e = 0; e < 2; e++) {
                const float* h3 = e ? h3B : h3A;
                u64 z0 = bdv.x, z1 = bdv.y;
#pragma unroll
                for (int k = 0; k < NU3; k++) {
                    u64 m = dup2(h3[k]);
                    ulonglong2 w = *(const ulonglong2*)(s + OFF_WD + k * 4);
                    z0 = ffma2(m, w.x, z0);
                    z1 = ffma2(m, w.y, z1);
                }
                u64 r0 = sigh2(z0, H2), r1 = sigh2(z1, H2);
                float o0, o1, o2, o3;
                unpack2(r0, o0, o1);
                unpack2(r1, o2, o3);
                float* op = (e ? oB : oA) + t * NOUT;
                *(float4*)op = make_float4(o0, o1, o2, o3);
            }
        }
    }
}

extern "C" void kernel_launch(void* const* d_in, const int* in_sizes, int n_in,
                              void* d_out, int out_size) {
    const float* x   = (const float*)d_in[0];
    const float* Wk1 = (const float*)d_in[1];
    const float* Wr1 = (const float*)d_in[2];
    const float* b1  = (const float*)d_in[3];
    const float* Wk2 = (const float*)d_in[4];
    const float* Wr2 = (const float*)d_in[5];
    const float* b2  = (const float*)d_in[6];
    const float* Wk3 = (const float*)d_in[7];
    const float* Wr3 = (const float*)d_in[8];
    const float* b3  = (const float*)d_in[9];
    const float* Wd  = (const float*)d_in[10];
    const float* bd  = (const float*)d_in[11];

    cudaFuncSetAttribute(lstm3_kernel, cudaFuncAttributeMaxDynamicSharedMemorySize, SMEM_BYTES);

    lstm3_kernel<<<NBATCH / EPB, NTHREADS, SMEM_BYTES>>>(
        x, Wk1, Wr1, b1, Wk2, Wr2, b2, Wk3, Wr3, b3, Wd, bd, (float*)d_out);
}